// round 6
// baseline (speedup 1.0000x reference)
#include <cuda_runtime.h>

#define NB 2
#define NT 2048
#define NC 1024
#define NHD 16
#define HS 64
#define WINSZ 256
#define MR (NB * NT)   // 4096 rows

// Scratch (allocation-free rule: device globals)
__device__ float g_q[NB * NHD * NT * HS];
__device__ float g_k[NB * NHD * NT * HS];
__device__ float g_v[NB * NHD * NT * HS];
__device__ float g_y[MR * NC];

// ---------------------------------------------------------------------------
// 128x128x8 register-blocked fp32 GEMM, 256 threads, 8x8 per thread.
// MODE 0: C = A @ Bm, scatter epilogue into g_q/g_k/g_v ([B,NH,T,HS])
// MODE 1: C = g_y @ Bm, plain row-major epilogue into Cout
// K is fixed at NC=1024. NVAL = N (3072 or 1024).
// ---------------------------------------------------------------------------
template<int NVAL, int MODE>
__global__ __launch_bounds__(256, 2)
void gemm128(const float* __restrict__ A, const float* __restrict__ Bm,
             float* __restrict__ Cout)
{
    __shared__ float As[8][128];   // [k][m]
    __shared__ float Bs[8][128];   // [k][n]

    const float* Ap = (MODE == 1) ? g_y : A;

    const int tid = threadIdx.x;
    const int tx = tid & 15;
    const int ty = tid >> 4;
    const int row0 = blockIdx.y * 128;
    const int col0 = blockIdx.x * 128;

    // load assignments (one float4 from A and one from B per k-tile)
    const int a_r = tid >> 1;            // 0..127
    const int a_c = (tid & 1) * 4;       // 0 or 4
    const int b_r = tid >> 5;            // 0..7
    const int b_c = (tid & 31) * 4;      // 0..124

    const float* Aptr = Ap + (size_t)(row0 + a_r) * NC + a_c;
    const float* Bptr = Bm + (size_t)b_r * NVAL + col0 + b_c;

    float acc[8][8];
#pragma unroll
    for (int i = 0; i < 8; i++)
#pragma unroll
        for (int j = 0; j < 8; j++) acc[i][j] = 0.f;

    for (int k0 = 0; k0 < NC; k0 += 8) {
        float4 av = *(const float4*)(Aptr + k0);
        float4 bv = *(const float4*)(Bptr + (size_t)k0 * NVAL);
        As[a_c + 0][a_r] = av.x;
        As[a_c + 1][a_r] = av.y;
        As[a_c + 2][a_r] = av.z;
        As[a_c + 3][a_r] = av.w;
        *(float4*)&Bs[b_r][b_c] = bv;
        __syncthreads();

#pragma unroll
        for (int k = 0; k < 8; k++) {
            float4 a0 = *(const float4*)&As[k][ty * 8];
            float4 a1 = *(const float4*)&As[k][ty * 8 + 4];
            float4 b0 = *(const float4*)&Bs[k][tx * 8];
            float4 b1 = *(const float4*)&Bs[k][tx * 8 + 4];
            float a[8] = {a0.x, a0.y, a0.z, a0.w, a1.x, a1.y, a1.z, a1.w};
            float b[8] = {b0.x, b0.y, b0.z, b0.w, b1.x, b1.y, b1.z, b1.w};
#pragma unroll
            for (int i = 0; i < 8; i++)
#pragma unroll
                for (int j = 0; j < 8; j++)
                    acc[i][j] = fmaf(a[i], b[j], acc[i][j]);
        }
        __syncthreads();
    }

    const int m0 = row0 + ty * 8;
    const int n0 = col0 + tx * 8;

    if (MODE == 0) {
        // scatter into q/k/v with [B, NH, T, HS] layout
        const int sect = n0 >> 10;                  // constant per block
        float* dstbase = (sect == 0) ? g_q : (sect == 1) ? g_k : g_v;
        const int c0 = n0 & (NC - 1);
        const int h = c0 >> 6;
        const int d0 = c0 & 63;                     // 8-aligned, within one head
#pragma unroll
        for (int i = 0; i < 8; i++) {
            const int m = m0 + i;
            const int bb = m >> 11;                 // / NT
            const int t = m & (NT - 1);
            float* drow = dstbase + (((size_t)(bb * NHD + h) * NT + t) * HS + d0);
            *(float4*)&drow[0] = make_float4(acc[i][0], acc[i][1], acc[i][2], acc[i][3]);
            *(float4*)&drow[4] = make_float4(acc[i][4], acc[i][5], acc[i][6], acc[i][7]);
        }
    } else {
#pragma unroll
        for (int i = 0; i < 8; i++) {
            float* drow = Cout + (size_t)(m0 + i) * NVAL + n0;
            *(float4*)&drow[0] = make_float4(acc[i][0], acc[i][1], acc[i][2], acc[i][3]);
            *(float4*)&drow[4] = make_float4(acc[i][4], acc[i][5], acc[i][6], acc[i][7]);
        }
    }
}

// ---------------------------------------------------------------------------
// Fused sliding-window attention, flash-style online softmax.
// Grid: (T/64, NH, B). Block: 256 threads (16x16 logical).
// Q tile 64 rows, key tiles of 64, at most 5 tiles per Q tile (window 256).
// Softmax stats kept fully in registers, replicated across the 16 tx lanes
// owning each row (reduced via shfl over 16 lanes).
// ---------------------------------------------------------------------------
#define SPITCH 68
#define TILE_F (64 * SPITCH)

__global__ __launch_bounds__(256)
void attn_kernel()
{
    extern __shared__ float sm[];
    float* Qs = sm;                 // [d][i] transposed, pre-scaled by 1/8
    float* Ks = sm + TILE_F;        // [d][j] transposed
    float* Vs = sm + 2 * TILE_F;    // [j][d]
    float* Ps = sm + 3 * TILE_F;    // [j][i]

    const int tid = threadIdx.x;
    const int tx = tid & 15;
    const int ty = tid >> 4;
    const int qb = blockIdx.x * 64;
    const int h = blockIdx.y;
    const int b = blockIdx.z;

    const size_t base = (size_t)(b * NHD + h) * NT * HS;
    const float* Q = g_q + base;
    const float* K = g_k + base;
    const float* V = g_v + base;

    // Load Q tile transposed + scaled
    for (int idx = tid; idx < 64 * 64; idx += 256) {
        const int i = idx >> 6;
        const int d = idx & 63;
        Qs[d * SPITCH + i] = Q[(size_t)(qb + i) * HS + d] * 0.125f;
    }

    float m[4], l[4], o[4][4];
#pragma unroll
    for (int i = 0; i < 4; i++) {
        m[i] = -1e30f;
        l[i] = 0.f;
#pragma unroll
        for (int j = 0; j < 4; j++) o[i][j] = 0.f;
    }

    const int tm = qb >> 6;
    const int t0 = (tm >= 4) ? tm - 4 : 0;
    const int ibase = qb + ty * 4;

    for (int kt = t0; kt <= tm; kt++) {
        const int kb = kt * 64;
        // load K (transposed) and V (natural)
        for (int idx = tid; idx < 64 * 64; idx += 256) {
            const int j = idx >> 6;
            const int d = idx & 63;
            Ks[d * SPITCH + j] = K[(size_t)(kb + j) * HS + d];
            Vs[j * SPITCH + d] = V[(size_t)(kb + j) * HS + d];
        }
        __syncthreads();

        // S = (Q/8) @ K^T  -> 4x4 per thread
        float s[4][4];
#pragma unroll
        for (int i = 0; i < 4; i++)
#pragma unroll
            for (int j = 0; j < 4; j++) s[i][j] = 0.f;

#pragma unroll 8
        for (int d = 0; d < 64; d++) {
            float4 qa = *(const float4*)&Qs[d * SPITCH + ty * 4];
            float4 kb4 = *(const float4*)&Ks[d * SPITCH + tx * 4];
            float a[4] = {qa.x, qa.y, qa.z, qa.w};
            float c[4] = {kb4.x, kb4.y, kb4.z, kb4.w};
#pragma unroll
            for (int i = 0; i < 4; i++)
#pragma unroll
                for (int j = 0; j < 4; j++)
                    s[i][j] = fmaf(a[i], c[j], s[i][j]);
        }

        // mask (causal + window)
        const int jbase = kb + tx * 4;
#pragma unroll
        for (int i = 0; i < 4; i++) {
            const int gi = ibase + i;
#pragma unroll
            for (int j = 0; j < 4; j++) {
                const int gj = jbase + j;
                if (gj > gi || gi - gj >= WINSZ) s[i][j] = -1e30f;
            }
        }

        // online softmax update per row
#pragma unroll
        for (int i = 0; i < 4; i++) {
            float rm = fmaxf(fmaxf(s[i][0], s[i][1]), fmaxf(s[i][2], s[i][3]));
            rm = fmaxf(rm, __shfl_xor_sync(0xffffffffu, rm, 1));
            rm = fmaxf(rm, __shfl_xor_sync(0xffffffffu, rm, 2));
            rm = fmaxf(rm, __shfl_xor_sync(0xffffffffu, rm, 4));
            rm = fmaxf(rm, __shfl_xor_sync(0xffffffffu, rm, 8));
            const float mn = fmaxf(m[i], rm);
            const float sc = __expf(m[i] - mn);
            float rs = 0.f;
#pragma unroll
            for (int j = 0; j < 4; j++) {
                const float p = __expf(s[i][j] - mn);
                s[i][j] = p;
                rs += p;
            }
            rs += __shfl_xor_sync(0xffffffffu, rs, 1);
            rs += __shfl_xor_sync(0xffffffffu, rs, 2);
            rs += __shfl_xor_sync(0xffffffffu, rs, 4);
            rs += __shfl_xor_sync(0xffffffffu, rs, 8);
            l[i] = l[i] * sc + rs;
            m[i] = mn;
#pragma unroll
            for (int j = 0; j < 4; j++) o[i][j] *= sc;
        }

        // write P transposed [j][i]
#pragma unroll
        for (int i = 0; i < 4; i++)
#pragma unroll
            for (int j = 0; j < 4; j++)
                Ps[(tx * 4 + j) * SPITCH + (ty * 4 + i)] = s[i][j];
        __syncthreads();

        // O += P @ V  -> 4 rows x 4 dims per thread
#pragma unroll 8
        for (int j = 0; j < 64; j++) {
            float4 pv = *(const float4*)&Ps[j * SPITCH + ty * 4];
            float4 vv = *(const float4*)&Vs[j * SPITCH + tx * 4];
            float p[4] = {pv.x, pv.y, pv.z, pv.w};
            float v[4] = {vv.x, vv.y, vv.z, vv.w};
#pragma unroll
            for (int i = 0; i < 4; i++)
#pragma unroll
                for (int d = 0; d < 4; d++)
                    o[i][d] = fmaf(p[i], v[d], o[i][d]);
        }
        __syncthreads();
    }

    // write y in [B, T, C] layout (ready for projection GEMM)
#pragma unroll
    for (int i = 0; i < 4; i++) {
        const float inv = 1.f / l[i];
        const int t = qb + ty * 4 + i;
        float* row = g_y + (size_t)(b * NT + t) * NC + h * HS + tx * 4;
        *(float4*)row = make_float4(o[i][0] * inv, o[i][1] * inv,
                                    o[i][2] * inv, o[i][3] * inv);
    }
}

// ---------------------------------------------------------------------------
extern "C" void kernel_launch(void* const* d_in, const int* in_sizes, int n_in,
                              void* d_out, int out_size)
{
    const float* x      = (const float*)d_in[0];  // [B,T,C]
    const float* W_attn = (const float*)d_in[1];  // [C,3C]
    const float* W_proj = (const float*)d_in[2];  // [C,C]
    float* out = (float*)d_out;                   // [B,T,C]

    const int smem_attn = 4 * TILE_F * (int)sizeof(float);   // 69632 B
    cudaFuncSetAttribute((const void*)attn_kernel,
                         cudaFuncAttributeMaxDynamicSharedMemorySize, smem_attn);

    // 1) QKV projection + scatter into [B,NH,T,HS]
    gemm128<3 * NC, 0><<<dim3(3 * NC / 128, MR / 128), 256>>>(x, W_attn, nullptr);

    // 2) fused sliding-window attention -> g_y [B,T,C]
    attn_kernel<<<dim3(NT / 64, NHD, NB), 256, smem_attn>>>();

    // 3) output projection
    gemm128<NC, 1><<<dim3(NC / 128, MR / 128), 256>>>(nullptr, W_proj, out);
}

// round 9
// speedup vs baseline: 3.6432x; 3.6432x over previous
#include <cuda_runtime.h>
#include <cuda_bf16.h>

#define NB 2
#define NT 2048
#define NC 1024
#define NHD 16
#define HS 64
#define WINSZ 256
#define MR (NB * NT)   // 4096 rows

// ---------------- device-global scratch (allocation-free rule) --------------
__device__ __align__(256) __nv_bfloat16 g_xh[MR * NC], g_xl[MR * NC];
__device__ __align__(256) __nv_bfloat16 g_wah[3 * NC * NC], g_wal[3 * NC * NC]; // W_attn^T [3072,1024]
__device__ __align__(256) __nv_bfloat16 g_wph[NC * NC], g_wpl[NC * NC];         // W_proj^T [1024,1024]
__device__ __align__(256) __nv_bfloat16 g_yh[MR * NC], g_yl[MR * NC];
__device__ __align__(256) float g_q[MR * NC], g_k[MR * NC], g_v[MR * NC];

// ---------------- helpers ---------------------------------------------------
__device__ __forceinline__ unsigned smem_u32(const void* p) {
    unsigned a;
    asm("{ .reg .u64 t; cvta.to.shared.u64 t, %1; cvt.u32.u64 %0, t; }"
        : "=r"(a) : "l"(p));
    return a;
}

__device__ __forceinline__ void ldsm4(unsigned& r0, unsigned& r1, unsigned& r2,
                                      unsigned& r3, unsigned addr) {
    asm volatile("ldmatrix.sync.aligned.m8n8.x4.shared.b16 {%0,%1,%2,%3}, [%4];"
                 : "=r"(r0), "=r"(r1), "=r"(r2), "=r"(r3) : "r"(addr));
}

__device__ __forceinline__ void mma16816(float* d, const unsigned* a, const unsigned* b) {
    asm volatile("mma.sync.aligned.m16n8k16.row.col.f32.bf16.bf16.f32 "
                 "{%0,%1,%2,%3}, {%4,%5,%6,%7}, {%8,%9}, {%0,%1,%2,%3};"
                 : "+f"(d[0]), "+f"(d[1]), "+f"(d[2]), "+f"(d[3])
                 : "r"(a[0]), "r"(a[1]), "r"(a[2]), "r"(a[3]),
                   "r"(b[0]), "r"(b[1]));
}

union Pack4 { __nv_bfloat16 b[4]; uint2 u; };

__device__ __forceinline__ void split1(float v, __nv_bfloat16& h, __nv_bfloat16& l) {
    h = __float2bfloat16(v);
    l = __float2bfloat16(v - __bfloat162float(h));
}

// ---------------- prep kernels ----------------------------------------------
__global__ __launch_bounds__(256)
void splitx_kernel(const float4* __restrict__ x) {
    int i = blockIdx.x * 256 + threadIdx.x;    // over MR*NC/4 float4s
    float4 v = x[i];
    Pack4 h, l;
    split1(v.x, h.b[0], l.b[0]);
    split1(v.y, h.b[1], l.b[1]);
    split1(v.z, h.b[2], l.b[2]);
    split1(v.w, h.b[3], l.b[3]);
    ((uint2*)g_xh)[i] = h.u;
    ((uint2*)g_xl)[i] = l.u;
}

// transpose + split: W [K=1024, NCOLS] -> Wt [NCOLS, 1024] bf16 hi/lo
template<int NCOLS, int WHICH>
__global__ __launch_bounds__(256)
void tsplit_kernel(const float* __restrict__ W) {
    __shared__ float tile[32][33];
    __nv_bfloat16* Th = WHICH ? g_wph : g_wah;
    __nv_bfloat16* Tl = WHICH ? g_wpl : g_wal;
    const int tx = threadIdx.x, ty = threadIdx.y;
    const int j0 = blockIdx.x * 32;   // N dim
    const int i0 = blockIdx.y * 32;   // K dim
#pragma unroll
    for (int r = 0; r < 32; r += 8)
        tile[ty + r][tx] = W[(size_t)(i0 + ty + r) * NCOLS + j0 + tx];
    __syncthreads();
#pragma unroll
    for (int r = 0; r < 32; r += 8) {
        float v = tile[tx][ty + r];            // = W[i0+tx][j0+ty+r]
        size_t o = (size_t)(j0 + ty + r) * NC + i0 + tx;
        __nv_bfloat16 h, l;
        split1(v, h, l);
        Th[o] = h;
        Tl[o] = l;
    }
}

// ---------------- split-bf16 HMMA GEMM --------------------------------------
// C[m, n] = sum_k A[m,k] * Bt[n,k]  (A, Bt row-major K-contiguous bf16 hi/lo)
// CTA tile 128x128, 8 warps (4M x 2N), warp tile 32x64. K-chunk 64 (128B SW128
// rows). Double-buffered cp.async. 3 MMA passes: AhBh + AhBl + AlBh.
// MODE 0: A = g_xh/g_xl, B = g_wah/g_wal, scatter epilogue -> g_q/g_k/g_v
// MODE 1: A = g_yh/g_yl, B = g_wph/g_wpl, row-major epilogue -> Cout
#define GEMM_TB   16384                          // one tile: 128 rows x 128B
#define GEMM_BUF  (4 * GEMM_TB)                  // Ah Al Bh Bl
#define GEMM_SMEM (2 * GEMM_BUF)                 // 131072 bytes

template<int MODE>
__global__ __launch_bounds__(256, 1)
void hgemm(float* __restrict__ Cout) {
    extern __shared__ __align__(1024) char sm[];
    const unsigned sb = smem_u32(sm);
    const int tid = threadIdx.x;
    const int wid = tid >> 5, lane = tid & 31;
    const int wm = wid & 3;          // 4 warps along M (32 rows each)
    const int wn = wid >> 2;         // 2 warps along N (64 cols each)
    const int col0 = blockIdx.x * 128;
    const int row0 = blockIdx.y * 128;

    const __nv_bfloat16* Ah = MODE ? g_yh : g_xh;
    const __nv_bfloat16* Al = MODE ? g_yl : g_xl;
    const __nv_bfloat16* Bh = MODE ? g_wph : g_wah;
    const __nv_bfloat16* Bl = MODE ? g_wpl : g_wal;

    // source row-base pointers (bytes), K row pitch = NC*2 = 2048 B
    const char* srcs[4];
    srcs[0] = (const char*)Ah + (size_t)row0 * 2048;
    srcs[1] = (const char*)Al + (size_t)row0 * 2048;
    srcs[2] = (const char*)Bh + (size_t)col0 * 2048;
    srcs[3] = (const char*)Bl + (size_t)col0 * 2048;

    auto load_chunk = [&](int c, int b) {
        const unsigned dst0 = sb + b * GEMM_BUF;
#pragma unroll
        for (int t = 0; t < 4; t++) {
#pragma unroll
            for (int i = 0; i < 4; i++) {
                const int unit = tid + i * 256;          // 0..1023
                const int r = unit >> 3, cc = unit & 7;
                const unsigned bo = r * 128 + cc * 16;
                const unsigned sw = bo ^ ((bo >> 3) & 0x70);
                const char* s = srcs[t] + (size_t)r * 2048 + c * 128 + cc * 16;
                const unsigned d = dst0 + t * GEMM_TB + sw;
                asm volatile("cp.async.cg.shared.global [%0], [%1], 16;"
                             :: "r"(d), "l"(s) : "memory");
            }
        }
        asm volatile("cp.async.commit_group;" ::: "memory");
    };

    float acc[2][8][4];
#pragma unroll
    for (int mt = 0; mt < 2; mt++)
#pragma unroll
        for (int nt = 0; nt < 8; nt++)
#pragma unroll
            for (int e = 0; e < 4; e++) acc[mt][nt][e] = 0.f;

    // per-lane ldmatrix row/half assignments
    const int arow_b = wm * 32 + (lane & 15);     // + mt*16
    const int ahalf = lane >> 4;                  // 0/1 -> k8 half
    const int brow_b = wn * 64 + ((lane >> 4) & 1) * 8 + (lane & 7);  // + pair*16
    const int bhalf = (lane >> 3) & 1;

    load_chunk(0, 0);

    for (int c = 0; c < 16; c++) {
        asm volatile("cp.async.wait_group 0;" ::: "memory");
        __syncthreads();
        if (c < 15) load_chunk(c + 1, (c + 1) & 1);

        const unsigned base = sb + (c & 1) * GEMM_BUF;
        const unsigned Ahb = base;
        const unsigned Alb = base + GEMM_TB;
        const unsigned Bhb = base + 2 * GEMM_TB;
        const unsigned Blb = base + 3 * GEMM_TB;

#pragma unroll
        for (int s = 0; s < 4; s++) {
            unsigned ah[2][4], al[2][4], bh[16], bl[16];
#pragma unroll
            for (int mt = 0; mt < 2; mt++) {
                const int row = arow_b + mt * 16;
                const unsigned off = row * 128 + (((2 * s + ahalf) ^ (row & 7)) * 16);
                ldsm4(ah[mt][0], ah[mt][1], ah[mt][2], ah[mt][3], Ahb + off);
                ldsm4(al[mt][0], al[mt][1], al[mt][2], al[mt][3], Alb + off);
            }
#pragma unroll
            for (int j = 0; j < 4; j++) {        // pair j covers n-tiles 2j, 2j+1
                const int row = brow_b + j * 16;
                const unsigned off = row * 128 + (((2 * s + bhalf) ^ (row & 7)) * 16);
                ldsm4(bh[4 * j], bh[4 * j + 1], bh[4 * j + 2], bh[4 * j + 3], Bhb + off);
                ldsm4(bl[4 * j], bl[4 * j + 1], bl[4 * j + 2], bl[4 * j + 3], Blb + off);
            }
#pragma unroll
            for (int mt = 0; mt < 2; mt++)
#pragma unroll
                for (int nt = 0; nt < 8; nt++) {
                    mma16816(acc[mt][nt], ah[mt], &bh[nt * 2]);
                    mma16816(acc[mt][nt], ah[mt], &bl[nt * 2]);
                    mma16816(acc[mt][nt], al[mt], &bh[nt * 2]);
                }
        }
        __syncthreads();
    }

    // -------- epilogue: acc lane layout: c0,c1 @ (m=lane/4, n=2*(lane%4)),
    //          c2,c3 @ (m=lane/4+8, same n) --------
    const int lm = lane >> 2;
    const int ln = (lane & 3) * 2;
#pragma unroll
    for (int mt = 0; mt < 2; mt++) {
        const int m0 = row0 + wm * 32 + mt * 16 + lm;
#pragma unroll
        for (int nt = 0; nt < 8; nt++) {
            const int gn = col0 + wn * 64 + nt * 8 + ln;
            if (MODE == 0) {
                const int sect = gn >> 10;
                float* basep = (sect == 0) ? g_q : (sect == 1) ? g_k : g_v;
                const int nn = gn & (NC - 1);
                const int hd = nn >> 6, dd = nn & 63;
#pragma unroll
                for (int half = 0; half < 2; half++) {
                    const int m = m0 + half * 8;
                    const int bb = m >> 11;
                    const int tt = m & (NT - 1);
                    float* dst = basep + (((size_t)(bb * NHD + hd) * NT + tt) * HS + dd);
                    *(float2*)dst = make_float2(acc[mt][nt][2 * half],
                                                acc[mt][nt][2 * half + 1]);
                }
            } else {
#pragma unroll
                for (int half = 0; half < 2; half++) {
                    const int m = m0 + half * 8;
                    float* dst = Cout + (size_t)m * NC + gn;
                    *(float2*)dst = make_float2(acc[mt][nt][2 * half],
                                                acc[mt][nt][2 * half + 1]);
                }
            }
        }
    }
}

// ---------------- fused sliding-window attention (fp32) ---------------------
#define SPITCH 68
#define TILE_F (64 * SPITCH)

__global__ __launch_bounds__(256)
void attn_kernel()
{
    extern __shared__ float smf[];
    float* Qs = smf;
    float* Ks = smf + TILE_F;
    float* Vs = smf + 2 * TILE_F;
    float* Ps = smf + 3 * TILE_F;

    const int tid = threadIdx.x;
    const int tx = tid & 15;
    const int ty = tid >> 4;
    const int qb = blockIdx.x * 64;
    const int h = blockIdx.y;
    const int b = blockIdx.z;

    const size_t base = (size_t)(b * NHD + h) * NT * HS;
    const float* Q = g_q + base;
    const float* K = g_k + base;
    const float* V = g_v + base;

    for (int idx = tid; idx < 64 * 64; idx += 256) {
        const int i = idx >> 6;
        const int d = idx & 63;
        Qs[d * SPITCH + i] = Q[(size_t)(qb + i) * HS + d] * 0.125f;
    }

    float m[4], l[4], o[4][4];
#pragma unroll
    for (int i = 0; i < 4; i++) {
        m[i] = -1e30f;
        l[i] = 0.f;
#pragma unroll
        for (int j = 0; j < 4; j++) o[i][j] = 0.f;
    }

    const int tm = qb >> 6;
    const int t0 = (tm >= 4) ? tm - 4 : 0;
    const int ibase = qb + ty * 4;

    for (int kt = t0; kt <= tm; kt++) {
        const int kb = kt * 64;
        for (int idx = tid; idx < 64 * 64; idx += 256) {
            const int j = idx >> 6;
            const int d = idx & 63;
            Ks[d * SPITCH + j] = K[(size_t)(kb + j) * HS + d];
            Vs[j * SPITCH + d] = V[(size_t)(kb + j) * HS + d];
        }
        __syncthreads();

        float s[4][4];
#pragma unroll
        for (int i = 0; i < 4; i++)
#pragma unroll
            for (int j = 0; j < 4; j++) s[i][j] = 0.f;

#pragma unroll 8
        for (int d = 0; d < 64; d++) {
            float4 qa = *(const float4*)&Qs[d * SPITCH + ty * 4];
            float4 kb4 = *(const float4*)&Ks[d * SPITCH + tx * 4];
            float a[4] = {qa.x, qa.y, qa.z, qa.w};
            float c[4] = {kb4.x, kb4.y, kb4.z, kb4.w};
#pragma unroll
            for (int i = 0; i < 4; i++)
#pragma unroll
                for (int j = 0; j < 4; j++)
                    s[i][j] = fmaf(a[i], c[j], s[i][j]);
        }

        const int jbase = kb + tx * 4;
#pragma unroll
        for (int i = 0; i < 4; i++) {
            const int gi = ibase + i;
#pragma unroll
            for (int j = 0; j < 4; j++) {
                const int gj = jbase + j;
                if (gj > gi || gi - gj >= WINSZ) s[i][j] = -1e30f;
            }
        }

#pragma unroll
        for (int i = 0; i < 4; i++) {
            float rm = fmaxf(fmaxf(s[i][0], s[i][1]), fmaxf(s[i][2], s[i][3]));
            rm = fmaxf(rm, __shfl_xor_sync(0xffffffffu, rm, 1));
            rm = fmaxf(rm, __shfl_xor_sync(0xffffffffu, rm, 2));
            rm = fmaxf(rm, __shfl_xor_sync(0xffffffffu, rm, 4));
            rm = fmaxf(rm, __shfl_xor_sync(0xffffffffu, rm, 8));
            const float mn = fmaxf(m[i], rm);
            const float sc = __expf(m[i] - mn);
            float rs = 0.f;
#pragma unroll
            for (int j = 0; j < 4; j++) {
                const float p = __expf(s[i][j] - mn);
                s[i][j] = p;
                rs += p;
            }
            rs += __shfl_xor_sync(0xffffffffu, rs, 1);
            rs += __shfl_xor_sync(0xffffffffu, rs, 2);
            rs += __shfl_xor_sync(0xffffffffu, rs, 4);
            rs += __shfl_xor_sync(0xffffffffu, rs, 8);
            l[i] = l[i] * sc + rs;
            m[i] = mn;
#pragma unroll
            for (int j = 0; j < 4; j++) o[i][j] *= sc;
        }

#pragma unroll
        for (int i = 0; i < 4; i++)
#pragma unroll
            for (int j = 0; j < 4; j++)
                Ps[(tx * 4 + j) * SPITCH + (ty * 4 + i)] = s[i][j];
        __syncthreads();

#pragma unroll 8
        for (int j = 0; j < 64; j++) {
            float4 pv = *(const float4*)&Ps[j * SPITCH + ty * 4];
            float4 vv = *(const float4*)&Vs[j * SPITCH + tx * 4];
            float p[4] = {pv.x, pv.y, pv.z, pv.w};
            float v[4] = {vv.x, vv.y, vv.z, vv.w};
#pragma unroll
            for (int i = 0; i < 4; i++)
#pragma unroll
                for (int d = 0; d < 4; d++)
                    o[i][d] = fmaf(p[i], v[d], o[i][d]);
        }
        __syncthreads();
    }

    // epilogue: split y into bf16 hi/lo for the projection GEMM
#pragma unroll
    for (int i = 0; i < 4; i++) {
        const float inv = 1.f / l[i];
        const int t = qb + ty * 4 + i;
        const size_t off = (size_t)(b * NT + t) * NC + h * HS + tx * 4;
        Pack4 ph, pl;
#pragma unroll
        for (int j = 0; j < 4; j++)
            split1(o[i][j] * inv, ph.b[j], pl.b[j]);
        *(uint2*)(g_yh + off) = ph.u;
        *(uint2*)(g_yl + off) = pl.u;
    }
}

// ---------------------------------------------------------------------------
extern "C" void kernel_launch(void* const* d_in, const int* in_sizes, int n_in,
                              void* d_out, int out_size)
{
    const float* x      = (const float*)d_in[0];  // [B,T,C]
    const float* W_attn = (const float*)d_in[1];  // [C,3C]
    const float* W_proj = (const float*)d_in[2];  // [C,C]
    float* out = (float*)d_out;                   // [B,T,C]

    const int smem_attn = 4 * TILE_F * (int)sizeof(float);   // 69632
    cudaFuncSetAttribute((const void*)attn_kernel,
                         cudaFuncAttributeMaxDynamicSharedMemorySize, smem_attn);
    cudaFuncSetAttribute((const void*)hgemm<0>,
                         cudaFuncAttributeMaxDynamicSharedMemorySize, GEMM_SMEM);
    cudaFuncSetAttribute((const void*)hgemm<1>,
                         cudaFuncAttributeMaxDynamicSharedMemorySize, GEMM_SMEM);

    // prep: split x, transpose+split weights
    splitx_kernel<<<MR * NC / 4 / 256, 256>>>((const float4*)x);
    tsplit_kernel<3 * NC, 0><<<dim3(3 * NC / 32, NC / 32), dim3(32, 8)>>>(W_attn);
    tsplit_kernel<NC, 1><<<dim3(NC / 32, NC / 32), dim3(32, 8)>>>(W_proj);

    // 1) QKV projection (HMMA) -> g_q/g_k/g_v
    hgemm<0><<<dim3(3 * NC / 128, MR / 128), 256, GEMM_SMEM>>>(nullptr);

    // 2) fused sliding-window attention -> g_yh/g_yl (bf16 split)
    attn_kernel<<<dim3(NT / 64, NHD, NB), 256, smem_attn>>>();

    // 3) output projection (HMMA) -> out
    hgemm<1><<<dim3(NC / 128, MR / 128), 256, GEMM_SMEM>>>(out);
}

// round 11
// speedup vs baseline: 3.9951x; 1.0966x over previous
#include <cuda_runtime.h>
#include <cuda_bf16.h>

#define NB 2
#define NT 2048
#define NC 1024
#define NHD 16
#define HS 64
#define WINSZ 256
#define MR (NB * NT)   // 4096 rows

// ---------------- device-global scratch (allocation-free rule) --------------
__device__ __align__(256) __nv_bfloat16 g_xh[MR * NC], g_xl[MR * NC];
__device__ __align__(256) __nv_bfloat16 g_wah[3 * NC * NC], g_wal[3 * NC * NC]; // W_attn^T [3072,1024]
__device__ __align__(256) __nv_bfloat16 g_wph[NC * NC], g_wpl[NC * NC];         // W_proj^T [1024,1024]
__device__ __align__(256) __nv_bfloat16 g_yh[MR * NC], g_yl[MR * NC];
__device__ __align__(256) float g_q[MR * NC], g_k[MR * NC], g_v[MR * NC];

// ---------------- helpers ---------------------------------------------------
__device__ __forceinline__ unsigned smem_u32(const void* p) {
    unsigned a;
    asm("{ .reg .u64 t; cvta.to.shared.u64 t, %1; cvt.u32.u64 %0, t; }"
        : "=r"(a) : "l"(p));
    return a;
}

__device__ __forceinline__ void ldsm4(unsigned& r0, unsigned& r1, unsigned& r2,
                                      unsigned& r3, unsigned addr) {
    asm volatile("ldmatrix.sync.aligned.m8n8.x4.shared.b16 {%0,%1,%2,%3}, [%4];"
                 : "=r"(r0), "=r"(r1), "=r"(r2), "=r"(r3) : "r"(addr));
}

__device__ __forceinline__ void mma16816(float* d, const unsigned* a, const unsigned* b) {
    asm volatile("mma.sync.aligned.m16n8k16.row.col.f32.bf16.bf16.f32 "
                 "{%0,%1,%2,%3}, {%4,%5,%6,%7}, {%8,%9}, {%0,%1,%2,%3};"
                 : "+f"(d[0]), "+f"(d[1]), "+f"(d[2]), "+f"(d[3])
                 : "r"(a[0]), "r"(a[1]), "r"(a[2]), "r"(a[3]),
                   "r"(b[0]), "r"(b[1]));
}

union Pack4 { __nv_bfloat16 b[4]; uint2 u; };

__device__ __forceinline__ void split1(float v, __nv_bfloat16& h, __nv_bfloat16& l) {
    h = __float2bfloat16(v);
    l = __float2bfloat16(v - __bfloat162float(h));
}

// ---------------- prep kernels ----------------------------------------------
__global__ __launch_bounds__(256)
void splitx_kernel(const float4* __restrict__ x) {
    int i = blockIdx.x * 256 + threadIdx.x;    // over MR*NC/4 float4s
    float4 v = x[i];
    Pack4 h, l;
    split1(v.x, h.b[0], l.b[0]);
    split1(v.y, h.b[1], l.b[1]);
    split1(v.z, h.b[2], l.b[2]);
    split1(v.w, h.b[3], l.b[3]);
    ((uint2*)g_xh)[i] = h.u;
    ((uint2*)g_xl)[i] = l.u;
}

// transpose + split: W [K=1024, NCOLS] -> Wt [NCOLS, 1024] bf16 hi/lo
template<int NCOLS, int WHICH>
__global__ __launch_bounds__(256)
void tsplit_kernel(const float* __restrict__ W) {
    __shared__ float tile[32][33];
    __nv_bfloat16* Th = WHICH ? g_wph : g_wah;
    __nv_bfloat16* Tl = WHICH ? g_wpl : g_wal;
    const int tx = threadIdx.x, ty = threadIdx.y;
    const int j0 = blockIdx.x * 32;   // N dim
    const int i0 = blockIdx.y * 32;   // K dim
#pragma unroll
    for (int r = 0; r < 32; r += 8)
        tile[ty + r][tx] = W[(size_t)(i0 + ty + r) * NCOLS + j0 + tx];
    __syncthreads();
#pragma unroll
    for (int r = 0; r < 32; r += 8) {
        float v = tile[tx][ty + r];            // = W[i0+tx][j0+ty+r]
        size_t o = (size_t)(j0 + ty + r) * NC + i0 + tx;
        __nv_bfloat16 h, l;
        split1(v, h, l);
        Th[o] = h;
        Tl[o] = l;
    }
}

// ---------------- split-bf16 HMMA GEMM --------------------------------------
// C[m, n] = sum_k A[m,k] * Bt[n,k]  (A, Bt row-major K-contiguous bf16 hi/lo)
// CTA tile 128(M) x 64(N), 4 warps along M, warp tile 32x64. K-chunk 64
// (128B SW128 rows). Double-buffered cp.async; 96KB smem -> 2 CTAs/SM.
// Register double-buffered ldmatrix fragments across the 4 k-substeps.
// 3 MMA passes: AhBh + AhBl + AlBh.
// MODE 0: A = g_xh/g_xl, B = g_wah/g_wal, scatter epilogue -> g_q/g_k/g_v
// MODE 1: A = g_yh/g_yl, B = g_wph/g_wpl, row-major epilogue -> Cout
#define GEMM_TA   16384                          // A tile: 128 rows x 128B
#define GEMM_TBB  8192                           // B tile:  64 rows x 128B
#define GEMM_BUF  (2 * GEMM_TA + 2 * GEMM_TBB)   // Ah Al Bh Bl = 49152
#define GEMM_SMEM (2 * GEMM_BUF)                 // 98304 bytes

struct Frag {
    unsigned ah[2][4], al[2][4];
    unsigned bh[16], bl[16];
};

template<int MODE>
__global__ __launch_bounds__(128, 2)
void hgemm(float* __restrict__ Cout) {
    extern __shared__ __align__(1024) char sm[];
    const unsigned sb = smem_u32(sm);
    const int tid = threadIdx.x;
    const int wm = tid >> 5, lane = tid & 31;    // 4 warps along M
    const int col0 = blockIdx.x * 64;
    const int row0 = blockIdx.y * 128;

    const __nv_bfloat16* Ah = MODE ? g_yh : g_xh;
    const __nv_bfloat16* Al = MODE ? g_yl : g_xl;
    const __nv_bfloat16* Bh = MODE ? g_wph : g_wah;
    const __nv_bfloat16* Bl = MODE ? g_wpl : g_wal;

    // source row-base pointers (bytes), K row pitch = NC*2 = 2048 B
    const char* srcA[2];
    const char* srcB[2];
    srcA[0] = (const char*)Ah + (size_t)row0 * 2048;
    srcA[1] = (const char*)Al + (size_t)row0 * 2048;
    srcB[0] = (const char*)Bh + (size_t)col0 * 2048;
    srcB[1] = (const char*)Bl + (size_t)col0 * 2048;

    auto load_chunk = [&](int c, int b) {
        const unsigned dst0 = sb + b * GEMM_BUF;
#pragma unroll
        for (int t = 0; t < 2; t++) {
#pragma unroll
            for (int i = 0; i < 8; i++) {
                const int unit = tid + i * 128;          // 0..1023
                const int r = unit >> 3, cc = unit & 7;
                const unsigned bo = r * 128 + cc * 16;
                const unsigned sw = bo ^ ((bo >> 3) & 0x70);
                const char* s = srcA[t] + (size_t)r * 2048 + c * 128 + cc * 16;
                asm volatile("cp.async.cg.shared.global [%0], [%1], 16;"
                             :: "r"(dst0 + t * GEMM_TA + sw), "l"(s) : "memory");
            }
        }
#pragma unroll
        for (int t = 0; t < 2; t++) {
#pragma unroll
            for (int i = 0; i < 4; i++) {
                const int unit = tid + i * 128;          // 0..511
                const int r = unit >> 3, cc = unit & 7;
                const unsigned bo = r * 128 + cc * 16;
                const unsigned sw = bo ^ ((bo >> 3) & 0x70);
                const char* s = srcB[t] + (size_t)r * 2048 + c * 128 + cc * 16;
                asm volatile("cp.async.cg.shared.global [%0], [%1], 16;"
                             :: "r"(dst0 + 2 * GEMM_TA + t * GEMM_TBB + sw), "l"(s)
                             : "memory");
            }
        }
        asm volatile("cp.async.commit_group;" ::: "memory");
    };

    float acc[2][8][4];
#pragma unroll
    for (int mt = 0; mt < 2; mt++)
#pragma unroll
        for (int nt = 0; nt < 8; nt++)
#pragma unroll
            for (int e = 0; e < 4; e++) acc[mt][nt][e] = 0.f;

    // per-lane ldmatrix row/half assignments
    const int arow_b = wm * 32 + (lane & 15);                 // + mt*16
    const int ahalf = lane >> 4;                              // k8 half
    const int brow_b = ((lane >> 4) & 1) * 8 + (lane & 7);    // + pair*16
    const int bhalf = (lane >> 3) & 1;

    Frag fr[2];

    auto fetch = [&](int s, Frag& f, unsigned base) {
#pragma unroll
        for (int mt = 0; mt < 2; mt++) {
            const int row = arow_b + mt * 16;
            const unsigned off = row * 128 + (((2 * s + ahalf) ^ (row & 7)) * 16);
            ldsm4(f.ah[mt][0], f.ah[mt][1], f.ah[mt][2], f.ah[mt][3], base + off);
            ldsm4(f.al[mt][0], f.al[mt][1], f.al[mt][2], f.al[mt][3],
                  base + GEMM_TA + off);
        }
#pragma unroll
        for (int j = 0; j < 4; j++) {          // pair j covers n-tiles 2j, 2j+1
            const int row = brow_b + j * 16;
            const unsigned off = row * 128 + (((2 * s + bhalf) ^ (row & 7)) * 16);
            ldsm4(f.bh[4 * j], f.bh[4 * j + 1], f.bh[4 * j + 2], f.bh[4 * j + 3],
                  base + 2 * GEMM_TA + off);
            ldsm4(f.bl[4 * j], f.bl[4 * j + 1], f.bl[4 * j + 2], f.bl[4 * j + 3],
                  base + 2 * GEMM_TA + GEMM_TBB + off);
        }
    };

    auto compute = [&](Frag& f) {
#pragma unroll
        for (int mt = 0; mt < 2; mt++)
#pragma unroll
            for (int nt = 0; nt < 8; nt++) {
                mma16816(acc[mt][nt], f.ah[mt], &f.bh[nt * 2]);
                mma16816(acc[mt][nt], f.ah[mt], &f.bl[nt * 2]);
                mma16816(acc[mt][nt], f.al[mt], &f.bh[nt * 2]);
            }
    };

    load_chunk(0, 0);

    for (int c = 0; c < 16; c++) {
        asm volatile("cp.async.wait_group 0;" ::: "memory");
        __syncthreads();
        if (c < 15) load_chunk(c + 1, (c + 1) & 1);

        const unsigned base = sb + (c & 1) * GEMM_BUF;
        fetch(0, fr[0], base);
#pragma unroll
        for (int s = 0; s < 4; s++) {
            if (s < 3) fetch(s + 1, fr[(s + 1) & 1], base);
            compute(fr[s & 1]);
        }
        __syncthreads();
    }

    // -------- epilogue: acc lane layout: c0,c1 @ (m=lane/4, n=2*(lane%4)),
    //          c2,c3 @ (m=lane/4+8, same n) --------
    const int lm = lane >> 2;
    const int ln = (lane & 3) * 2;
#pragma unroll
    for (int mt = 0; mt < 2; mt++) {
        const int m0 = row0 + wm * 32 + mt * 16 + lm;
#pragma unroll
        for (int nt = 0; nt < 8; nt++) {
            const int gn = col0 + nt * 8 + ln;
            if (MODE == 0) {
                const int sect = gn >> 10;
                float* basep = (sect == 0) ? g_q : (sect == 1) ? g_k : g_v;
                const int nn = gn & (NC - 1);
                const int hd = nn >> 6, dd = nn & 63;
#pragma unroll
                for (int half = 0; half < 2; half++) {
                    const int m = m0 + half * 8;
                    const int bb = m >> 11;
                    const int tt = m & (NT - 1);
                    float* dst = basep + (((size_t)(bb * NHD + hd) * NT + tt) * HS + dd);
                    *(float2*)dst = make_float2(acc[mt][nt][2 * half],
                                                acc[mt][nt][2 * half + 1]);
                }
            } else {
#pragma unroll
                for (int half = 0; half < 2; half++) {
                    const int m = m0 + half * 8;
                    float* dst = Cout + (size_t)m * NC + gn;
                    *(float2*)dst = make_float2(acc[mt][nt][2 * half],
                                                acc[mt][nt][2 * half + 1]);
                }
            }
        }
    }
}

// ---------------- fused sliding-window attention (fp32) ---------------------
#define SPITCH 68
#define TILE_F (64 * SPITCH)

__global__ __launch_bounds__(256)
void attn_kernel()
{
    extern __shared__ float smf[];
    float* Qs = smf;
    float* Ks = smf + TILE_F;
    float* Vs = smf + 2 * TILE_F;
    float* Ps = smf + 3 * TILE_F;

    const int tid = threadIdx.x;
    const int tx = tid & 15;
    const int ty = tid >> 4;
    const int qb = blockIdx.x * 64;
    const int h = blockIdx.y;
    const int b = blockIdx.z;

    const size_t base = (size_t)(b * NHD + h) * NT * HS;
    const float* Q = g_q + base;
    const float* K = g_k + base;
    const float* V = g_v + base;

    for (int idx = tid; idx < 64 * 64; idx += 256) {
        const int i = idx >> 6;
        const int d = idx & 63;
        Qs[d * SPITCH + i] = Q[(size_t)(qb + i) * HS + d] * 0.125f;
    }

    float m[4], l[4], o[4][4];
#pragma unroll
    for (int i = 0; i < 4; i++) {
        m[i] = -1e30f;
        l[i] = 0.f;
#pragma unroll
        for (int j = 0; j < 4; j++) o[i][j] = 0.f;
    }

    const int tm = qb >> 6;
    const int t0 = (tm >= 4) ? tm - 4 : 0;
    const int ibase = qb + ty * 4;

    for (int kt = t0; kt <= tm; kt++) {
        const int kb = kt * 64;
        for (int idx = tid; idx < 64 * 64; idx += 256) {
            const int j = idx >> 6;
            const int d = idx & 63;
            Ks[d * SPITCH + j] = K[(size_t)(kb + j) * HS + d];
            Vs[j * SPITCH + d] = V[(size_t)(kb + j) * HS + d];
        }
        __syncthreads();

        float s[4][4];
#pragma unroll
        for (int i = 0; i < 4; i++)
#pragma unroll
            for (int j = 0; j < 4; j++) s[i][j] = 0.f;

#pragma unroll 8
        for (int d = 0; d < 64; d++) {
            float4 qa = *(const float4*)&Qs[d * SPITCH + ty * 4];
            float4 kb4 = *(const float4*)&Ks[d * SPITCH + tx * 4];
            float a[4] = {qa.x, qa.y, qa.z, qa.w};
            float c[4] = {kb4.x, kb4.y, kb4.z, kb4.w};
#pragma unroll
            for (int i = 0; i < 4; i++)
#pragma unroll
                for (int j = 0; j < 4; j++)
                    s[i][j] = fmaf(a[i], c[j], s[i][j]);
        }

        const int jbase = kb + tx * 4;
#pragma unroll
        for (int i = 0; i < 4; i++) {
            const int gi = ibase + i;
#pragma unroll
            for (int j = 0; j < 4; j++) {
                const int gj = jbase + j;
                if (gj > gi || gi - gj >= WINSZ) s[i][j] = -1e30f;
            }
        }

#pragma unroll
        for (int i = 0; i < 4; i++) {
            float rm = fmaxf(fmaxf(s[i][0], s[i][1]), fmaxf(s[i][2], s[i][3]));
            rm = fmaxf(rm, __shfl_xor_sync(0xffffffffu, rm, 1));
            rm = fmaxf(rm, __shfl_xor_sync(0xffffffffu, rm, 2));
            rm = fmaxf(rm, __shfl_xor_sync(0xffffffffu, rm, 4));
            rm = fmaxf(rm, __shfl_xor_sync(0xffffffffu, rm, 8));
            const float mn = fmaxf(m[i], rm);
            const float sc = __expf(m[i] - mn);
            float rs = 0.f;
#pragma unroll
            for (int j = 0; j < 4; j++) {
                const float p = __expf(s[i][j] - mn);
                s[i][j] = p;
                rs += p;
            }
            rs += __shfl_xor_sync(0xffffffffu, rs, 1);
            rs += __shfl_xor_sync(0xffffffffu, rs, 2);
            rs += __shfl_xor_sync(0xffffffffu, rs, 4);
            rs += __shfl_xor_sync(0xffffffffu, rs, 8);
            l[i] = l[i] * sc + rs;
            m[i] = mn;
#pragma unroll
            for (int j = 0; j < 4; j++) o[i][j] *= sc;
        }

#pragma unroll
        for (int i = 0; i < 4; i++)
#pragma unroll
            for (int j = 0; j < 4; j++)
                Ps[(tx * 4 + j) * SPITCH + (ty * 4 + i)] = s[i][j];
        __syncthreads();

#pragma unroll 8
        for (int j = 0; j < 64; j++) {
            float4 pv = *(const float4*)&Ps[j * SPITCH + ty * 4];
            float4 vv = *(const float4*)&Vs[j * SPITCH + tx * 4];
            float p[4] = {pv.x, pv.y, pv.z, pv.w};
            float v[4] = {vv.x, vv.y, vv.z, vv.w};
#pragma unroll
            for (int i = 0; i < 4; i++)
#pragma unroll
                for (int d = 0; d < 4; d++)
                    o[i][d] = fmaf(p[i], v[d], o[i][d]);
        }
        __syncthreads();
    }

    // epilogue: split y into bf16 hi/lo for the projection GEMM
#pragma unroll
    for (int i = 0; i < 4; i++) {
        const float inv = 1.f / l[i];
        const int t = qb + ty * 4 + i;
        const size_t off = (size_t)(b * NT + t) * NC + h * HS + tx * 4;
        Pack4 ph, pl;
#pragma unroll
        for (int j = 0; j < 4; j++)
            split1(o[i][j] * inv, ph.b[j], pl.b[j]);
        *(uint2*)(g_yh + off) = ph.u;
        *(uint2*)(g_yl + off) = pl.u;
    }
}

// ---------------------------------------------------------------------------
extern "C" void kernel_launch(void* const* d_in, const int* in_sizes, int n_in,
                              void* d_out, int out_size)
{
    const float* x      = (const float*)d_in[0];  // [B,T,C]
    const float* W_attn = (const float*)d_in[1];  // [C,3C]
    const float* W_proj = (const float*)d_in[2];  // [C,C]
    float* out = (float*)d_out;                   // [B,T,C]

    const int smem_attn = 4 * TILE_F * (int)sizeof(float);   // 69632
    cudaFuncSetAttribute((const void*)attn_kernel,
                         cudaFuncAttributeMaxDynamicSharedMemorySize, smem_attn);
    cudaFuncSetAttribute((const void*)hgemm<0>,
                         cudaFuncAttributeMaxDynamicSharedMemorySize, GEMM_SMEM);
    cudaFuncSetAttribute((const void*)hgemm<1>,
                         cudaFuncAttributeMaxDynamicSharedMemorySize, GEMM_SMEM);

    // prep: split x, transpose+split weights
    splitx_kernel<<<MR * NC / 4 / 256, 256>>>((const float4*)x);
    tsplit_kernel<3 * NC, 0><<<dim3(3 * NC / 32, NC / 32), dim3(32, 8)>>>(W_attn);
    tsplit_kernel<NC, 1><<<dim3(NC / 32, NC / 32), dim3(32, 8)>>>(W_proj);

    // 1) QKV projection (HMMA) -> g_q/g_k/g_v
    hgemm<0><<<dim3(3 * NC / 64, MR / 128), 128, GEMM_SMEM>>>(nullptr);

    // 2) fused sliding-window attention -> g_yh/g_yl (bf16 split)
    attn_kernel<<<dim3(NT / 64, NHD, NB), 256, smem_attn>>>();

    // 3) output projection (HMMA) -> out
    hgemm<1><<<dim3(NC / 64, MR / 128), 128, GEMM_SMEM>>>(out);
}

// round 12
// speedup vs baseline: 5.5896x; 1.3991x over previous
#include <cuda_runtime.h>
#include <cuda_bf16.h>

#define NB 2
#define NT 2048
#define NC 1024
#define NHD 16
#define HS 64
#define WINSZ 256
#define MR (NB * NT)   // 4096 rows

// ---------------- device-global scratch (allocation-free rule) --------------
__device__ __align__(256) __nv_bfloat16 g_xh[MR * NC], g_xl[MR * NC];
__device__ __align__(256) __nv_bfloat16 g_wah[3 * NC * NC], g_wal[3 * NC * NC]; // W_attn^T
__device__ __align__(256) __nv_bfloat16 g_wph[NC * NC], g_wpl[NC * NC];         // W_proj^T
__device__ __align__(256) __nv_bfloat16 g_yh[MR * NC], g_yl[MR * NC];
// attention operands, bf16 hi/lo
__device__ __align__(256) __nv_bfloat16 g_qh[MR * NC], g_ql[MR * NC];   // [b,h,t,d] (pre-scaled 1/8)
__device__ __align__(256) __nv_bfloat16 g_kh[MR * NC], g_kl[MR * NC];   // [b,h,t,d]
__device__ __align__(256) __nv_bfloat16 g_vth[MR * NC], g_vtl[MR * NC]; // [b,h,d,t] (transposed)

// ---------------- helpers ---------------------------------------------------
__device__ __forceinline__ unsigned smem_u32(const void* p) {
    unsigned a;
    asm("{ .reg .u64 t; cvta.to.shared.u64 t, %1; cvt.u32.u64 %0, t; }"
        : "=r"(a) : "l"(p));
    return a;
}

__device__ __forceinline__ void ldsm4(unsigned& r0, unsigned& r1, unsigned& r2,
                                      unsigned& r3, unsigned addr) {
    asm volatile("ldmatrix.sync.aligned.m8n8.x4.shared.b16 {%0,%1,%2,%3}, [%4];"
                 : "=r"(r0), "=r"(r1), "=r"(r2), "=r"(r3) : "r"(addr));
}

__device__ __forceinline__ void mma16816(float* d, const unsigned* a, const unsigned* b) {
    asm volatile("mma.sync.aligned.m16n8k16.row.col.f32.bf16.bf16.f32 "
                 "{%0,%1,%2,%3}, {%4,%5,%6,%7}, {%8,%9}, {%0,%1,%2,%3};"
                 : "+f"(d[0]), "+f"(d[1]), "+f"(d[2]), "+f"(d[3])
                 : "r"(a[0]), "r"(a[1]), "r"(a[2]), "r"(a[3]),
                   "r"(b[0]), "r"(b[1]));
}

union Pack4 { __nv_bfloat16 b[4]; uint2 u; };
union PackB2 { __nv_bfloat162 v; unsigned u; };

__device__ __forceinline__ unsigned u32bf(__nv_bfloat162 x) {
    PackB2 p; p.v = x; return p.u;
}

__device__ __forceinline__ void split1(float v, __nv_bfloat16& h, __nv_bfloat16& l) {
    h = __float2bfloat16(v);
    l = __float2bfloat16(v - __bfloat162float(h));
}

// split a pair to hi/lo bf16x2 words
__device__ __forceinline__ void split2(float a, float b, unsigned& hi, unsigned& lo) {
    __nv_bfloat162 h = __floats2bfloat162_rn(a, b);
    hi = u32bf(h);
    lo = u32bf(__floats2bfloat162_rn(a - __bfloat162float(h.x),
                                     b - __bfloat162float(h.y)));
}

// ---------------- prep kernels ----------------------------------------------
__global__ __launch_bounds__(256)
void splitx_kernel(const float4* __restrict__ x) {
    int i = blockIdx.x * 256 + threadIdx.x;    // over MR*NC/4 float4s
    float4 v = x[i];
    Pack4 h, l;
    split1(v.x, h.b[0], l.b[0]);
    split1(v.y, h.b[1], l.b[1]);
    split1(v.z, h.b[2], l.b[2]);
    split1(v.w, h.b[3], l.b[3]);
    ((uint2*)g_xh)[i] = h.u;
    ((uint2*)g_xl)[i] = l.u;
}

// transpose + split: W [K=1024, NCOLS] -> Wt [NCOLS, 1024] bf16 hi/lo
template<int NCOLS, int WHICH>
__global__ __launch_bounds__(256)
void tsplit_kernel(const float* __restrict__ W) {
    __shared__ float tile[32][33];
    __nv_bfloat16* Th = WHICH ? g_wph : g_wah;
    __nv_bfloat16* Tl = WHICH ? g_wpl : g_wal;
    const int tx = threadIdx.x, ty = threadIdx.y;
    const int j0 = blockIdx.x * 32;   // N dim
    const int i0 = blockIdx.y * 32;   // K dim
#pragma unroll
    for (int r = 0; r < 32; r += 8)
        tile[ty + r][tx] = W[(size_t)(i0 + ty + r) * NCOLS + j0 + tx];
    __syncthreads();
#pragma unroll
    for (int r = 0; r < 32; r += 8) {
        float v = tile[tx][ty + r];
        size_t o = (size_t)(j0 + ty + r) * NC + i0 + tx;
        __nv_bfloat16 h, l;
        split1(v, h, l);
        Th[o] = h;
        Tl[o] = l;
    }
}

// ---------------- split-bf16 HMMA GEMM --------------------------------------
// CTA tile 128(M) x 64(N), 4 warps along M. K-chunk 64 (128B SW128 rows).
// MODE 0: A = g_xh/g_xl, B = g_wah/g_wal, epilogue -> bf16 hi/lo q/k/vt
// MODE 1: A = g_yh/g_yl, B = g_wph/g_wpl, row-major f32 epilogue -> Cout
#define GEMM_TA   16384
#define GEMM_TBB  8192
#define GEMM_BUF  (2 * GEMM_TA + 2 * GEMM_TBB)   // 49152
#define GEMM_SMEM (2 * GEMM_BUF)                 // 98304

struct Frag {
    unsigned ah[2][4], al[2][4];
    unsigned bh[16], bl[16];
};

template<int MODE>
__global__ __launch_bounds__(128, 2)
void hgemm(float* __restrict__ Cout) {
    extern __shared__ __align__(1024) char sm[];
    const unsigned sb = smem_u32(sm);
    const int tid = threadIdx.x;
    const int wm = tid >> 5, lane = tid & 31;
    const int col0 = blockIdx.x * 64;
    const int row0 = blockIdx.y * 128;

    const __nv_bfloat16* Ah = MODE ? g_yh : g_xh;
    const __nv_bfloat16* Al = MODE ? g_yl : g_xl;
    const __nv_bfloat16* Bh = MODE ? g_wph : g_wah;
    const __nv_bfloat16* Bl = MODE ? g_wpl : g_wal;

    const char* srcA[2];
    const char* srcB[2];
    srcA[0] = (const char*)Ah + (size_t)row0 * 2048;
    srcA[1] = (const char*)Al + (size_t)row0 * 2048;
    srcB[0] = (const char*)Bh + (size_t)col0 * 2048;
    srcB[1] = (const char*)Bl + (size_t)col0 * 2048;

    auto load_chunk = [&](int c, int b) {
        const unsigned dst0 = sb + b * GEMM_BUF;
#pragma unroll
        for (int t = 0; t < 2; t++) {
#pragma unroll
            for (int i = 0; i < 8; i++) {
                const int unit = tid + i * 128;
                const int r = unit >> 3, cc = unit & 7;
                const unsigned bo = r * 128 + cc * 16;
                const unsigned sw = bo ^ ((bo >> 3) & 0x70);
                const char* s = srcA[t] + (size_t)r * 2048 + c * 128 + cc * 16;
                asm volatile("cp.async.cg.shared.global [%0], [%1], 16;"
                             :: "r"(dst0 + t * GEMM_TA + sw), "l"(s) : "memory");
            }
        }
#pragma unroll
        for (int t = 0; t < 2; t++) {
#pragma unroll
            for (int i = 0; i < 4; i++) {
                const int unit = tid + i * 128;
                const int r = unit >> 3, cc = unit & 7;
                const unsigned bo = r * 128 + cc * 16;
                const unsigned sw = bo ^ ((bo >> 3) & 0x70);
                const char* s = srcB[t] + (size_t)r * 2048 + c * 128 + cc * 16;
                asm volatile("cp.async.cg.shared.global [%0], [%1], 16;"
                             :: "r"(dst0 + 2 * GEMM_TA + t * GEMM_TBB + sw), "l"(s)
                             : "memory");
            }
        }
        asm volatile("cp.async.commit_group;" ::: "memory");
    };

    float acc[2][8][4];
#pragma unroll
    for (int mt = 0; mt < 2; mt++)
#pragma unroll
        for (int nt = 0; nt < 8; nt++)
#pragma unroll
            for (int e = 0; e < 4; e++) acc[mt][nt][e] = 0.f;

    const int arow_b = wm * 32 + (lane & 15);
    const int ahalf = lane >> 4;
    const int brow_b = ((lane >> 4) & 1) * 8 + (lane & 7);
    const int bhalf = (lane >> 3) & 1;

    Frag fr[2];

    auto fetch = [&](int s, Frag& f, unsigned base) {
#pragma unroll
        for (int mt = 0; mt < 2; mt++) {
            const int row = arow_b + mt * 16;
            const unsigned off = row * 128 + (((2 * s + ahalf) ^ (row & 7)) * 16);
            ldsm4(f.ah[mt][0], f.ah[mt][1], f.ah[mt][2], f.ah[mt][3], base + off);
            ldsm4(f.al[mt][0], f.al[mt][1], f.al[mt][2], f.al[mt][3],
                  base + GEMM_TA + off);
        }
#pragma unroll
        for (int j = 0; j < 4; j++) {
            const int row = brow_b + j * 16;
            const unsigned off = row * 128 + (((2 * s + bhalf) ^ (row & 7)) * 16);
            ldsm4(f.bh[4 * j], f.bh[4 * j + 1], f.bh[4 * j + 2], f.bh[4 * j + 3],
                  base + 2 * GEMM_TA + off);
            ldsm4(f.bl[4 * j], f.bl[4 * j + 1], f.bl[4 * j + 2], f.bl[4 * j + 3],
                  base + 2 * GEMM_TA + GEMM_TBB + off);
        }
    };

    auto compute = [&](Frag& f) {
#pragma unroll
        for (int mt = 0; mt < 2; mt++)
#pragma unroll
            for (int nt = 0; nt < 8; nt++) {
                mma16816(acc[mt][nt], f.ah[mt], &f.bh[nt * 2]);
                mma16816(acc[mt][nt], f.ah[mt], &f.bl[nt * 2]);
                mma16816(acc[mt][nt], f.al[mt], &f.bh[nt * 2]);
            }
    };

    load_chunk(0, 0);

    for (int c = 0; c < 16; c++) {
        asm volatile("cp.async.wait_group 0;" ::: "memory");
        __syncthreads();
        if (c < 15) load_chunk(c + 1, (c + 1) & 1);

        const unsigned base = sb + (c & 1) * GEMM_BUF;
        fetch(0, fr[0], base);
#pragma unroll
        for (int s = 0; s < 4; s++) {
            if (s < 3) fetch(s + 1, fr[(s + 1) & 1], base);
            compute(fr[s & 1]);
        }
        __syncthreads();
    }

    // -------- epilogue --------
    const int lm = lane >> 2;
    const int ln = (lane & 3) * 2;
#pragma unroll
    for (int mt = 0; mt < 2; mt++) {
        const int m0 = row0 + wm * 32 + mt * 16 + lm;
#pragma unroll
        for (int nt = 0; nt < 8; nt++) {
            const int gn = col0 + nt * 8 + ln;
            if (MODE == 0) {
                const int sect = gn >> 10;
                const int nn = gn & (NC - 1);
                const int hd = nn >> 6, dd = nn & 63;
#pragma unroll
                for (int half = 0; half < 2; half++) {
                    const int m = m0 + half * 8;
                    const int bb = m >> 11;
                    const int tt = m & (NT - 1);
                    float v0 = acc[mt][nt][2 * half];
                    float v1 = acc[mt][nt][2 * half + 1];
                    if (sect == 0) { v0 *= 0.125f; v1 *= 0.125f; }
                    unsigned hi, lo;
                    split2(v0, v1, hi, lo);
                    if (sect < 2) {
                        const size_t off =
                            ((size_t)(bb * NHD + hd) * NT + tt) * HS + dd;
                        if (sect == 0) {
                            *(unsigned*)&g_qh[off] = hi;
                            *(unsigned*)&g_ql[off] = lo;
                        } else {
                            *(unsigned*)&g_kh[off] = hi;
                            *(unsigned*)&g_kl[off] = lo;
                        }
                    } else {
                        const size_t ob =
                            ((size_t)(bb * NHD + hd) * HS + dd) * NT + tt;
                        PackB2 ph, pl2;
                        ph.u = hi; pl2.u = lo;
                        g_vth[ob] = ph.v.x;
                        g_vth[ob + NT] = ph.v.y;
                        g_vtl[ob] = pl2.v.x;
                        g_vtl[ob + NT] = pl2.v.y;
                    }
                }
            } else {
#pragma unroll
                for (int half = 0; half < 2; half++) {
                    const int m = m0 + half * 8;
                    float* dst = Cout + (size_t)m * NC + gn;
                    *(float2*)dst = make_float2(acc[mt][nt][2 * half],
                                                acc[mt][nt][2 * half + 1]);
                }
            }
        }
    }
}

// ---------------- HMMA sliding-window flash attention ------------------------
// CTA: 64 queries x 1 head, 128 threads (4 warps x 16 rows).
// S = QK^T 3-pass split-bf16; softmax fp32 on fragments; P repacked
// register-direct to A-fragments (hi/lo); O += 3-pass P @ V^T.
// Smem: Q hi/lo 16KB + double-buffered K/V hi/lo tiles 2x32KB = 80KB.
#define ATTN_SMEM (16384 + 2 * 32768)

__global__ __launch_bounds__(128, 2)
void attn_mma() {
    extern __shared__ __align__(1024) char smraw[];
    const unsigned sb = smem_u32(smraw);
    const int tid = threadIdx.x;
    const int wm = tid >> 5, lane = tid & 31;
    const int qb = blockIdx.x * 64;
    const int h = blockIdx.y, b = blockIdx.z;

    const size_t bh = (size_t)(b * NHD + h);
    const __nv_bfloat16* Qhp = g_qh + (bh * NT + qb) * HS;
    const __nv_bfloat16* Qlp = g_ql + (bh * NT + qb) * HS;
    const __nv_bfloat16* Khp = g_kh + bh * NT * HS;
    const __nv_bfloat16* Klp = g_kl + bh * NT * HS;
    const __nv_bfloat16* Vhp = g_vth + bh * (size_t)HS * NT;
    const __nv_bfloat16* Vlp = g_vtl + bh * (size_t)HS * NT;

    auto ld_tile = [&](unsigned dst, const __nv_bfloat16* src, int pitchB) {
#pragma unroll
        for (int i = 0; i < 4; i++) {
            const int unit = tid + i * 128;
            const int r = unit >> 3, cc = unit & 7;
            const unsigned d = dst + r * 128 + ((cc ^ (r & 7)) * 16);
            const char* s = (const char*)src + (size_t)r * pitchB + cc * 16;
            asm volatile("cp.async.cg.shared.global [%0], [%1], 16;"
                         :: "r"(d), "l"(s) : "memory");
        }
    };

    auto kvload = [&](int kt, int buf) {
        const int kb = kt * 64;
        const unsigned kvb = sb + 16384 + buf * 32768;
        ld_tile(kvb,         Khp + (size_t)kb * HS, 128);
        ld_tile(kvb + 8192,  Klp + (size_t)kb * HS, 128);
        ld_tile(kvb + 16384, Vhp + kb, NT * 2);
        ld_tile(kvb + 24576, Vlp + kb, NT * 2);
        asm volatile("cp.async.commit_group;" ::: "memory");
    };

    const int tm = qb >> 6;
    const int t0 = (tm >= 4) ? tm - 4 : 0;

    ld_tile(sb, Qhp, 128);
    ld_tile(sb + 8192, Qlp, 128);
    asm volatile("cp.async.commit_group;" ::: "memory");
    kvload(t0, t0 & 1);
    asm volatile("cp.async.wait_group 0;" ::: "memory");
    __syncthreads();

    // Q fragments (held in registers for the whole CTA lifetime)
    unsigned qfh[4][4], qfl[4][4];
    const int arow = wm * 16 + (lane & 15);
    const int ahalf = lane >> 4;
#pragma unroll
    for (int s = 0; s < 4; s++) {
        const unsigned off = arow * 128 + (((2 * s + ahalf) ^ (arow & 7)) * 16);
        ldsm4(qfh[s][0], qfh[s][1], qfh[s][2], qfh[s][3], sb + off);
        ldsm4(qfl[s][0], qfl[s][1], qfl[s][2], qfl[s][3], sb + 8192 + off);
    }

    const int brow_b = ((lane >> 4) & 1) * 8 + (lane & 7);
    const int bhalf = (lane >> 3) & 1;

    float m0 = -1e30f, m1 = -1e30f, l0 = 0.f, l1 = 0.f;
    float o[8][4];
#pragma unroll
    for (int nt = 0; nt < 8; nt++)
#pragma unroll
        for (int e = 0; e < 4; e++) o[nt][e] = 0.f;

    const int i0r = qb + wm * 16 + (lane >> 2);
    const int i1r = i0r + 8;
    const int jc = 2 * (lane & 3);

    for (int kt = t0; kt <= tm; kt++) {
        const unsigned kvb = sb + 16384 + (kt & 1) * 32768;
        if (kt < tm) kvload(kt + 1, (kt + 1) & 1);

        // ---- S = Q @ K^T ----
        float sacc[8][4];
#pragma unroll
        for (int nt = 0; nt < 8; nt++)
#pragma unroll
            for (int e = 0; e < 4; e++) sacc[nt][e] = 0.f;

#pragma unroll
        for (int s = 0; s < 4; s++) {
            unsigned kfh[16], kfl[16];
#pragma unroll
            for (int j = 0; j < 4; j++) {
                const int row = brow_b + j * 16;
                const unsigned off = row * 128 + (((2 * s + bhalf) ^ (row & 7)) * 16);
                ldsm4(kfh[4 * j], kfh[4 * j + 1], kfh[4 * j + 2], kfh[4 * j + 3],
                      kvb + off);
                ldsm4(kfl[4 * j], kfl[4 * j + 1], kfl[4 * j + 2], kfl[4 * j + 3],
                      kvb + 8192 + off);
            }
#pragma unroll
            for (int nt = 0; nt < 8; nt++) {
                mma16816(sacc[nt], qfh[s], &kfh[nt * 2]);
                mma16816(sacc[nt], qfh[s], &kfl[nt * 2]);
                mma16816(sacc[nt], qfl[s], &kfh[nt * 2]);
            }
        }

        // ---- mask ----
        const int kb = kt * 64;
        if (kt == tm) {
#pragma unroll
            for (int nt = 0; nt < 8; nt++) {
                const int j0 = kb + nt * 8 + jc;
                if (j0 > i0r)     sacc[nt][0] = -1e30f;
                if (j0 + 1 > i0r) sacc[nt][1] = -1e30f;
                if (j0 > i1r)     sacc[nt][2] = -1e30f;
                if (j0 + 1 > i1r) sacc[nt][3] = -1e30f;
            }
        } else if (kt == tm - 4) {
#pragma unroll
            for (int nt = 0; nt < 8; nt++) {
                const int j0 = kb + nt * 8 + jc;
                if (i0r - j0 >= WINSZ)       sacc[nt][0] = -1e30f;
                if (i0r - (j0 + 1) >= WINSZ) sacc[nt][1] = -1e30f;
                if (i1r - j0 >= WINSZ)       sacc[nt][2] = -1e30f;
                if (i1r - (j0 + 1) >= WINSZ) sacc[nt][3] = -1e30f;
            }
        }

        // ---- online softmax (rows i0r: c0,c1 / i1r: c2,c3) ----
        float rm0 = -1e30f, rm1 = -1e30f;
#pragma unroll
        for (int nt = 0; nt < 8; nt++) {
            rm0 = fmaxf(rm0, fmaxf(sacc[nt][0], sacc[nt][1]));
            rm1 = fmaxf(rm1, fmaxf(sacc[nt][2], sacc[nt][3]));
        }
        rm0 = fmaxf(rm0, __shfl_xor_sync(0xffffffffu, rm0, 1));
        rm0 = fmaxf(rm0, __shfl_xor_sync(0xffffffffu, rm0, 2));
        rm1 = fmaxf(rm1, __shfl_xor_sync(0xffffffffu, rm1, 1));
        rm1 = fmaxf(rm1, __shfl_xor_sync(0xffffffffu, rm1, 2));
        const float mn0 = fmaxf(fmaxf(m0, rm0), -1e20f);
        const float mn1 = fmaxf(fmaxf(m1, rm1), -1e20f);
        const float sc0 = __expf(m0 - mn0);
        const float sc1 = __expf(m1 - mn1);
        m0 = mn0; m1 = mn1;
        float rs0 = 0.f, rs1 = 0.f;
#pragma unroll
        for (int nt = 0; nt < 8; nt++) {
            sacc[nt][0] = __expf(sacc[nt][0] - mn0); rs0 += sacc[nt][0];
            sacc[nt][1] = __expf(sacc[nt][1] - mn0); rs0 += sacc[nt][1];
            sacc[nt][2] = __expf(sacc[nt][2] - mn1); rs1 += sacc[nt][2];
            sacc[nt][3] = __expf(sacc[nt][3] - mn1); rs1 += sacc[nt][3];
        }
        rs0 += __shfl_xor_sync(0xffffffffu, rs0, 1);
        rs0 += __shfl_xor_sync(0xffffffffu, rs0, 2);
        rs1 += __shfl_xor_sync(0xffffffffu, rs1, 1);
        rs1 += __shfl_xor_sync(0xffffffffu, rs1, 2);
        l0 = l0 * sc0 + rs0;
        l1 = l1 * sc1 + rs1;
#pragma unroll
        for (int nt = 0; nt < 8; nt++) {
            o[nt][0] *= sc0; o[nt][1] *= sc0;
            o[nt][2] *= sc1; o[nt][3] *= sc1;
        }

        // ---- O += P @ V^T ----
#pragma unroll
        for (int s = 0; s < 4; s++) {          // key k16 block = ntiles 2s,2s+1
            unsigned ph[4], pl[4];
            split2(sacc[2 * s][0], sacc[2 * s][1], ph[0], pl[0]);
            split2(sacc[2 * s][2], sacc[2 * s][3], ph[1], pl[1]);
            split2(sacc[2 * s + 1][0], sacc[2 * s + 1][1], ph[2], pl[2]);
            split2(sacc[2 * s + 1][2], sacc[2 * s + 1][3], ph[3], pl[3]);

            unsigned vfh[16], vfl[16];
#pragma unroll
            for (int j = 0; j < 4; j++) {
                const int row = brow_b + j * 16;
                const unsigned off = row * 128 + (((2 * s + bhalf) ^ (row & 7)) * 16);
                ldsm4(vfh[4 * j], vfh[4 * j + 1], vfh[4 * j + 2], vfh[4 * j + 3],
                      kvb + 16384 + off);
                ldsm4(vfl[4 * j], vfl[4 * j + 1], vfl[4 * j + 2], vfl[4 * j + 3],
                      kvb + 24576 + off);
            }
#pragma unroll
            for (int nt = 0; nt < 8; nt++) {
                mma16816(o[nt], ph, &vfh[nt * 2]);
                mma16816(o[nt], ph, &vfl[nt * 2]);
                mma16816(o[nt], pl, &vfh[nt * 2]);
            }
        }

        if (kt < tm) {
            asm volatile("cp.async.wait_group 0;" ::: "memory");
            __syncthreads();
        }
    }

    // ---- epilogue: y = O / l, split to bf16 hi/lo [B,T,C] ----
    const float inv0 = 1.f / l0;
    const float inv1 = 1.f / l1;
    const size_t orow0 = ((size_t)b * NT + (qb + wm * 16 + (lane >> 2))) * NC + h * HS;
    const size_t orow1 = orow0 + (size_t)8 * NC;
#pragma unroll
    for (int nt = 0; nt < 8; nt++) {
        const int d = nt * 8 + jc;
        unsigned hi, lo;
        split2(o[nt][0] * inv0, o[nt][1] * inv0, hi, lo);
        *(unsigned*)&g_yh[orow0 + d] = hi;
        *(unsigned*)&g_yl[orow0 + d] = lo;
        split2(o[nt][2] * inv1, o[nt][3] * inv1, hi, lo);
        *(unsigned*)&g_yh[orow1 + d] = hi;
        *(unsigned*)&g_yl[orow1 + d] = lo;
    }
}

// ---------------------------------------------------------------------------
extern "C" void kernel_launch(void* const* d_in, const int* in_sizes, int n_in,
                              void* d_out, int out_size)
{
    const float* x      = (const float*)d_in[0];  // [B,T,C]
    const float* W_attn = (const float*)d_in[1];  // [C,3C]
    const float* W_proj = (const float*)d_in[2];  // [C,C]
    float* out = (float*)d_out;                   // [B,T,C]

    cudaFuncSetAttribute((const void*)attn_mma,
                         cudaFuncAttributeMaxDynamicSharedMemorySize, ATTN_SMEM);
    cudaFuncSetAttribute((const void*)hgemm<0>,
                         cudaFuncAttributeMaxDynamicSharedMemorySize, GEMM_SMEM);
    cudaFuncSetAttribute((const void*)hgemm<1>,
                         cudaFuncAttributeMaxDynamicSharedMemorySize, GEMM_SMEM);

    // prep: split x, transpose+split weights
    splitx_kernel<<<MR * NC / 4 / 256, 256>>>((const float4*)x);
    tsplit_kernel<3 * NC, 0><<<dim3(3 * NC / 32, NC / 32), dim3(32, 8)>>>(W_attn);
    tsplit_kernel<NC, 1><<<dim3(NC / 32, NC / 32), dim3(32, 8)>>>(W_proj);

    // 1) QKV projection (HMMA) -> bf16 hi/lo Q/K (row) + V (transposed)
    hgemm<0><<<dim3(3 * NC / 64, MR / 128), 128, GEMM_SMEM>>>(nullptr);

    // 2) HMMA sliding-window attention -> g_yh/g_yl (bf16 split)
    attn_mma<<<dim3(NT / 64, NHD, NB), 128, ATTN_SMEM>>>();

    // 3) output projection (HMMA) -> out
    hgemm<1><<<dim3(NC / 64, MR / 128), 128, GEMM_SMEM>>>(out);
}